// round 8
// baseline (speedup 1.0000x reference)
#include <cuda_runtime.h>
#include <mma.h>
#include <math.h>

using namespace nvcuda;

#define NB 8192

// ---------------- device scratch ----------------
__device__ float  g_y1[(size_t)NB * 64 * 14 * 14];   // conv1 pre-BN output
__device__ float  g_y2[(size_t)NB * 128 * 7 * 7];    // conv2 pre-BN output
__device__ double g_acc[448];
__device__ float  g_scale[224];
__device__ float  g_shift[224];

__device__ __forceinline__ float tf32r(float x) {
    float y;
    asm("cvt.rna.tf32.f32 %0, %1;" : "=f"(y) : "f"(x));
    return y;
}

// ---------------- zero stats ----------------
__global__ void k_zero() {
    int i = blockIdx.x * blockDim.x + threadIdx.x;
    if (i < 448) g_acc[i] = 0.0;
}

// ---------------- stage0 stats: conv0 (+bias), accumulate sum/sumsq ----------------
__global__ void __launch_bounds__(256) k_stats0(const float* __restrict__ x,
                                                const float* __restrict__ w0,
                                                const float* __restrict__ b0) {
    __shared__ float sx[30 * 28];
    __shared__ float sw[288];
    __shared__ float sb[32];
    __shared__ float ssum[32], ssq[32];
    int tid = threadIdx.x;
    int n = blockIdx.x;
    const float* xim = x + (size_t)n * 784;
    for (int i = tid; i < 840; i += 256) {
        int r = i / 28;
        sx[i] = (r >= 1 && r <= 28) ? xim[i - 28] : 0.f;
    }
    for (int i = tid; i < 288; i += 256) sw[i] = w0[i];
    if (tid < 32) { sb[tid] = b0[tid]; ssum[tid] = 0.f; ssq[tid] = 0.f; }
    __syncthreads();

#define LDROW(SR, X0, X1, X2) { const float* _p = &sx[(SR) * 28 + col]; \
        X0 = mL ? _p[-1] : 0.f; X1 = _p[0]; X2 = mR ? _p[1] : 0.f; }

    for (int task = tid; task < 896; task += 256) {
        int c = task / 28, col = task % 28;
        float w[9];
#pragma unroll
        for (int i = 0; i < 9; i++) w[i] = sw[c * 9 + i];
        float bias = sb[c];
        bool mL = col > 0, mR = col < 27;
        float a0, a1, a2, d0, d1, d2, e0, e1, e2;
        LDROW(0, a0, a1, a2);
        LDROW(1, d0, d1, d2);
        float ls = 0.f, lq = 0.f;
        for (int r = 0; r < 28; r++) {
            LDROW(r + 2, e0, e1, e2);
            float acc = bias;
            acc += w[0] * a0 + w[1] * a1 + w[2] * a2;
            acc += w[3] * d0 + w[4] * d1 + w[5] * d2;
            acc += w[6] * e0 + w[7] * e1 + w[8] * e2;
            ls += acc; lq += acc * acc;
            a0 = d0; a1 = d1; a2 = d2;
            d0 = e0; d1 = e1; d2 = e2;
        }
        atomicAdd(&ssum[c], ls);
        atomicAdd(&ssq[c], lq);
    }
    __syncthreads();
    if (tid < 32) {
        atomicAdd(&g_acc[tid], (double)ssum[tid]);
        atomicAdd(&g_acc[32 + tid], (double)ssq[tid]);
    }
}

// ---------------- finalize BN ----------------
__global__ void k_fin(int acc_off, int C, double inv_n,
                      const float* __restrict__ g, const float* __restrict__ be, int so) {
    int c = threadIdx.x;
    if (c < C) {
        double mean = g_acc[acc_off + c] * inv_n;
        double var = g_acc[acc_off + C + c] * inv_n - mean * mean;
        float s = g[c] * rsqrtf((float)var + 1e-5f);
        g_scale[so + c] = s;
        g_shift[so + c] = be[c] - (float)mean * s;
    }
}

// ---------------- fused conv0+bn0+relu -> conv1 (WMMA tf32), store y1, stats1 ----
// block = half image, 256 threads (8 warps).
// GEMM: C[64co][98p] = W1[64][128k] x B[128k][98p]
//   B[k=(ci,ky,kx)][p=(oh,ow)] = a0[ci][2oh+ky][2ow+kx]  (pure permutation of a0)
// smem floats: B [128][136] 17408 | W [64][136] 8704 | sx 448 | sw0 288 | sb0 32
//              | ssum 64 | ssq 64  = 27008 fl = 108032 B  (2 blocks/SM)
// C (64x112 used) is stored over the B region after the MMA phase.
__global__ void __launch_bounds__(256, 2) k_conv1(const float* __restrict__ x,
                                                  const float* __restrict__ w0,
                                                  const float* __restrict__ b0,
                                                  const float* __restrict__ w1,
                                                  const float* __restrict__ b1) {
    extern __shared__ float sm[];
    float* B    = sm;            // [128][136]
    float* W    = sm + 17408;    // [64][136]
    float* sx   = sm + 26112;    // [16][28]
    float* sw0  = sm + 26560;    // 288
    float* sb0  = sm + 26848;    // 32
    float* ssum = sm + 26880;    // 64
    float* ssq  = sm + 26944;    // 64

    int tid = threadIdx.x;
    int n = blockIdx.x >> 1;
    int half = blockIdx.x & 1;
    int r0 = half * 14;
    const float* xim = x + (size_t)n * 784;

    for (int i = tid; i < 448; i += 256) {
        int lr = i / 28;
        int gr = r0 - 1 + lr;
        sx[i] = (gr >= 0 && gr < 28) ? xim[gr * 28 + (i % 28)] : 0.f;
    }
    for (int i = tid; i < 288; i += 256) sw0[i] = w0[i];
    if (tid < 32) sb0[tid] = b0[tid];
    if (tid < 64) { ssum[tid] = 0.f; ssq[tid] = 0.f; }
    // weights -> smem (tf32-rounded), row-major [co][k], ldm 136
    for (int i = tid; i < 8192; i += 256) {
        int co = i >> 7, k = i & 127;
        W[co * 136 + k] = tf32r(w1[i]);
    }
    // zero B pad columns p=98..111 (Ntile 6 reads up to col 111)
    for (int i = tid; i < 1792; i += 256) {
        B[(i / 14) * 136 + 98 + (i % 14)] = 0.f;
    }
    __syncthreads();

#define LDX(SR, X0, X1, X2) { const float* _p = &sx[(SR) * 28 + col]; \
        X0 = mL ? _p[-1] : 0.f; X1 = _p[0]; X2 = mR ? _p[1] : 0.f; }

    // conv0 + bn0 + relu -> B rows (im2col permutation), tf32-rounded
    for (int task = tid; task < 896; task += 256) {
        int c = task / 28, col = task % 28;
        float w[9];
#pragma unroll
        for (int i = 0; i < 9; i++) w[i] = sw0[c * 9 + i];
        float bias = sb0[c];
        float sc = g_scale[c], sh = g_shift[c];
        bool mL = col > 0, mR = col < 27;
        int rbase = c * 4 + (col & 1);        // + ky*2 added per row
        int p0 = col >> 1;                     // + oh*14 added per row
        float a0, a1, a2, d0, d1, d2, e0, e1, e2;
        LDX(0, a0, a1, a2);
        LDX(1, d0, d1, d2);
#pragma unroll 2
        for (int lr = 0; lr < 14; lr++) {
            LDX(lr + 2, e0, e1, e2);
            float acc = bias;
            acc += w[0] * a0 + w[1] * a1 + w[2] * a2;
            acc += w[3] * d0 + w[4] * d1 + w[5] * d2;
            acc += w[6] * e0 + w[7] * e1 + w[8] * e2;
            float v = fmaxf(fmaf(acc, sc, sh), 0.f);
            int row = rbase + (lr & 1) * 2;
            int p = (lr >> 1) * 14 + p0;
            B[row * 136 + p] = tf32r(v);
            a0 = d0; a1 = d1; a2 = d2;
            d0 = e0; d1 = e1; d2 = e2;
        }
    }
    __syncthreads();

    // WMMA: warps 0..6 each own one Ntile (16 p-cols), all 4 Mtiles
    int wpi = tid >> 5;
    wmma::fragment<wmma::accumulator, 16, 16, 8, float> cf[4];
    if (wpi < 7) {
#pragma unroll
        for (int m = 0; m < 4; m++) wmma::fill_fragment(cf[m], 0.f);
        wmma::fragment<wmma::matrix_a, 16, 16, 8, wmma::precision::tf32, wmma::row_major> af;
        wmma::fragment<wmma::matrix_b, 16, 16, 8, wmma::precision::tf32, wmma::row_major> bf;
#pragma unroll 4
        for (int ks = 0; ks < 16; ks++) {
            wmma::load_matrix_sync(bf, &B[ks * 8 * 136 + wpi * 16], 136);
#pragma unroll
            for (int m = 0; m < 4; m++) {
                wmma::load_matrix_sync(af, &W[m * 16 * 136 + ks * 8], 136);
                wmma::mma_sync(cf[m], af, bf, cf[m]);
            }
        }
    }
    __syncthreads();   // all B reads done -> store C over B region
    if (wpi < 7) {
#pragma unroll
        for (int m = 0; m < 4; m++)
            wmma::store_matrix_sync(&B[m * 16 * 136 + wpi * 16], cf[m], 136,
                                    wmma::mem_row_major);
    }
    __syncthreads();

    // bias + stats + y1 write (p 0..97 contiguous in y1)
    {
        int co = tid >> 2, q = tid & 3;
        int p0 = q * 25, cnt = (q < 3) ? 25 : 23;
        float bias = b1[co];
        float ls = 0.f, lq = 0.f;
        float* dst = g_y1 + ((size_t)(n * 64 + co) * 14 + half * 7) * 14;
        const float* src = &B[co * 136 + p0];
#pragma unroll 5
        for (int i = 0; i < cnt; i++) {
            float v = src[i] + bias;
            dst[p0 + i] = v;
            ls += v; lq += v * v;
        }
        atomicAdd(&ssum[co], ls);
        atomicAdd(&ssq[co], lq);
    }
    __syncthreads();
    if (tid < 64) {
        atomicAdd(&g_acc[64 + tid], (double)ssum[tid]);
        atomicAdd(&g_acc[128 + tid], (double)ssq[tid]);
    }
}

// ---------------- fused bn1+relu -> conv2 (WMMA tf32), store y2, stats2 --------
// block = 1 image, 256 threads (8 warps), grid NB.
// GEMM: C[128co][49p] = W2[128][256k] x B[256k][49p], K split in 2 chunks of 128.
// smem floats: B [128][72] 9216 | Wc [128][136] 17408 | ssum 128 | ssq 128
//   = 26880 fl = 107520 B (2 blocks/SM). C (128x64) stored over B region.
__global__ void __launch_bounds__(256, 2) k_conv2(const float* __restrict__ w2,
                                                  const float* __restrict__ b2) {
    extern __shared__ float sm[];
    float* B    = sm;            // [128][72]
    float* Wc   = sm + 9216;     // [128][136]
    float* ssum = sm + 26624;    // 128
    float* ssq  = sm + 26752;    // 128
    int tid = threadIdx.x;
    int n = blockIdx.x;
    if (tid < 128) { ssum[tid] = 0.f; ssq[tid] = 0.f; }

    // zero B pad columns p=49..63 (Ntile 3 reads up to col 63)
    for (int i = tid; i < 1920; i += 256) {
        B[(i / 15) * 72 + 49 + (i % 15)] = 0.f;
    }

    int wpi = tid >> 5;
    int Nt = wpi & 3, Mg = wpi >> 2;       // Ntile, Mtile group (4 tiles each)
    wmma::fragment<wmma::accumulator, 16, 16, 8, float> cf[4];
#pragma unroll
    for (int m = 0; m < 4; m++) wmma::fill_fragment(cf[m], 0.f);
    wmma::fragment<wmma::matrix_a, 16, 16, 8, wmma::precision::tf32, wmma::row_major> af;
    wmma::fragment<wmma::matrix_b, 16, 16, 8, wmma::precision::tf32, wmma::row_major> bf;

    for (int kc = 0; kc < 2; kc++) {
        __syncthreads();   // previous-phase B/Wc reads done
        // W chunk [128co][128k], tf32-rounded
        for (int i = tid; i < 16384; i += 256) {
            int co = i >> 7, kl = i & 127;
            Wc[co * 136 + kl] = tf32r(w2[co * 256 + kc * 128 + kl]);
        }
        // B chunk: y1 + bn1 + relu, im2col permutation (32 ci x 196 pix, float2)
        for (int i = tid; i < 3136; i += 256) {
            int ci = i / 98, rem = i % 98;
            int r = rem / 7, q = rem % 7;
            int cig = kc * 32 + ci;
            float sc = g_scale[32 + cig], sh = g_shift[32 + cig];
            float2 v = *(const float2*)(g_y1 + ((size_t)(n * 64 + cig)) * 196 + r * 14 + 2 * q);
            float e = fmaxf(fmaf(v.x, sc, sh), 0.f);
            float o = fmaxf(fmaf(v.y, sc, sh), 0.f);
            int rb = (ci * 4 + (r & 1) * 2) * 72 + (r >> 1) * 7 + q;
            B[rb] = tf32r(e);
            B[rb + 72] = tf32r(o);
        }
        __syncthreads();
#pragma unroll 4
        for (int ks = 0; ks < 16; ks++) {
            wmma::load_matrix_sync(bf, &B[ks * 8 * 72 + Nt * 16], 72);
#pragma unroll
            for (int m = 0; m < 4; m++) {
                int Mt = Mg * 4 + m;
                wmma::load_matrix_sync(af, &Wc[Mt * 16 * 136 + ks * 8], 136);
                wmma::mma_sync(cf[m], af, bf, cf[m]);
            }
        }
    }
    __syncthreads();   // all B reads done -> store C over B region
#pragma unroll
    for (int m = 0; m < 4; m++) {
        int Mt = Mg * 4 + m;
        wmma::store_matrix_sync(&B[Mt * 16 * 72 + Nt * 16], cf[m], 72,
                                wmma::mem_row_major);
    }
    __syncthreads();

    // bias + stats + y2 write (p 0..48 contiguous)
    {
        int co = tid >> 1, hh = tid & 1;
        int p0 = hh * 25, cnt = hh ? 24 : 25;
        float bias = b2[co];
        float ls = 0.f, lq = 0.f;
        float* dst = g_y2 + (size_t)(n * 128 + co) * 49;
        const float* src = &B[co * 72 + p0];
#pragma unroll 5
        for (int i = 0; i < cnt; i++) {
            float v = src[i] + bias;
            dst[p0 + i] = v;
            ls += v; lq += v * v;
        }
        atomicAdd(&ssum[co], ls);
        atomicAdd(&ssq[co], lq);
    }
    __syncthreads();
    if (tid < 128) {
        atomicAdd(&g_acc[192 + tid], (double)ssum[tid]);
        atomicAdd(&g_acc[320 + tid], (double)ssq[tid]);
    }
}

// ---------------- bn2+relu + global avg pool + FC ----------------
__global__ void __launch_bounds__(128) k_head(const float* __restrict__ wfc,
                                              const float* __restrict__ bfc,
                                              float* __restrict__ out) {
    __shared__ float sraw[6272];
    __shared__ float pooled[128];
    int tid = threadIdx.x, n = blockIdx.x;
    const float* y2 = g_y2 + (size_t)n * 6272;
    for (int i = tid; i < 6272; i += 128) sraw[i] = y2[i];
    __syncthreads();
    {
        int c = tid;
        float sc = g_scale[96 + c], sh = g_shift[96 + c];
        float s = 0.f;
        const float* p = &sraw[c * 49];
#pragma unroll
        for (int i = 0; i < 49; i++) s += fmaxf(fmaf(p[i], sc, sh), 0.f);
        pooled[c] = s * (1.f / 49.f);
    }
    __syncthreads();
    if (tid < 10) {
        float o = bfc[tid];
        const float* wr = wfc + tid * 128;
#pragma unroll 8
        for (int c = 0; c < 128; c++) o = fmaf(pooled[c], wr[c], o);
        out[(size_t)n * 10 + tid] = o;
    }
}

// ---------------- launch ----------------
extern "C" void kernel_launch(void* const* d_in, const int* in_sizes, int n_in,
                              void* d_out, int out_size) {
    const float* x   = (const float*)d_in[0];
    const float* w0  = (const float*)d_in[1];
    const float* b0  = (const float*)d_in[2];
    const float* g0  = (const float*)d_in[3];
    const float* be0 = (const float*)d_in[4];
    const float* w1  = (const float*)d_in[5];
    const float* b1  = (const float*)d_in[6];
    const float* g1  = (const float*)d_in[7];
    const float* be1 = (const float*)d_in[8];
    const float* w2  = (const float*)d_in[9];
    const float* b2  = (const float*)d_in[10];
    const float* g2  = (const float*)d_in[11];
    const float* be2 = (const float*)d_in[12];
    const float* wfc = (const float*)d_in[13];
    const float* bfc = (const float*)d_in[14];
    float* out = (float*)d_out;

    cudaFuncSetAttribute(k_conv1, cudaFuncAttributeMaxDynamicSharedMemorySize, 108032);
    cudaFuncSetAttribute(k_conv2, cudaFuncAttributeMaxDynamicSharedMemorySize, 107520);

    k_zero<<<2, 256>>>();
    k_stats0<<<NB, 256>>>(x, w0, b0);
    k_fin<<<1, 128>>>(0, 32, 1.0 / (8192.0 * 784.0), g0, be0, 0);
    k_conv1<<<NB * 2, 256, 108032>>>(x, w0, b0, w1, b1);
    k_fin<<<1, 128>>>(64, 64, 1.0 / (8192.0 * 196.0), g1, be1, 32);
    k_conv2<<<NB, 256, 107520>>>(w2, b2);
    k_fin<<<1, 128>>>(192, 128, 1.0 / (8192.0 * 49.0), g2, be2, 96);
    k_head<<<NB, 128>>>(wfc, bfc, out);
}

// round 11
// speedup vs baseline: 1.0630x; 1.0630x over previous
#include <cuda_runtime.h>
#include <mma.h>
#include <math.h>

using namespace nvcuda;

#define NB 8192

// ---------------- device scratch ----------------
// g_y0: conv0 pre-BN output (822MB). Dead after k_conv1 -> g_y2 aliases its head.
__device__ float  g_y0[(size_t)NB * 32 * 28 * 28];
__device__ float  g_y1[(size_t)NB * 64 * 14 * 14];   // conv1 pre-BN output
#define g_y2 g_y0                                     // conv2 pre-BN output (205MB), aliased
__device__ double g_acc[448];
__device__ float  g_scale[224];
__device__ float  g_shift[224];

__device__ __forceinline__ float tf32r(float x) {
    float y;
    asm("cvt.rna.tf32.f32 %0, %1;" : "=f"(y) : "f"(x));
    return y;
}

// ---------------- zero stats ----------------
__global__ void k_zero() {
    int i = blockIdx.x * blockDim.x + threadIdx.x;
    if (i < 448) g_acc[i] = 0.0;
}

// ---------------- stage0: conv0 (+bias) -> store y0, accumulate stats ----------------
__global__ void __launch_bounds__(256) k_stats0(const float* __restrict__ x,
                                                const float* __restrict__ w0,
                                                const float* __restrict__ b0) {
    __shared__ float sx[30 * 28];
    __shared__ float sw[288];
    __shared__ float sb[32];
    __shared__ float ssum[32], ssq[32];
    int tid = threadIdx.x;
    int n = blockIdx.x;
    const float* xim = x + (size_t)n * 784;
    for (int i = tid; i < 840; i += 256) {
        int r = i / 28;
        sx[i] = (r >= 1 && r <= 28) ? xim[i - 28] : 0.f;
    }
    for (int i = tid; i < 288; i += 256) sw[i] = w0[i];
    if (tid < 32) { sb[tid] = b0[tid]; ssum[tid] = 0.f; ssq[tid] = 0.f; }
    __syncthreads();

#define LDROW(SR, X0, X1, X2) { const float* _p = &sx[(SR) * 28 + col]; \
        X0 = mL ? _p[-1] : 0.f; X1 = _p[0]; X2 = mR ? _p[1] : 0.f; }

    for (int task = tid; task < 896; task += 256) {
        int c = task / 28, col = task % 28;
        float w[9];
#pragma unroll
        for (int i = 0; i < 9; i++) w[i] = sw[c * 9 + i];
        float bias = sb[c];
        bool mL = col > 0, mR = col < 27;
        float* ydst = g_y0 + ((size_t)(n * 32 + c)) * 784 + col;
        float a0, a1, a2, d0, d1, d2, e0, e1, e2;
        LDROW(0, a0, a1, a2);
        LDROW(1, d0, d1, d2);
        float ls = 0.f, lq = 0.f;
        for (int r = 0; r < 28; r++) {
            LDROW(r + 2, e0, e1, e2);
            float acc = bias;
            acc += w[0] * a0 + w[1] * a1 + w[2] * a2;
            acc += w[3] * d0 + w[4] * d1 + w[5] * d2;
            acc += w[6] * e0 + w[7] * e1 + w[8] * e2;
            ydst[r * 28] = acc;
            ls += acc; lq += acc * acc;
            a0 = d0; a1 = d1; a2 = d2;
            d0 = e0; d1 = e1; d2 = e2;
        }
        atomicAdd(&ssum[c], ls);
        atomicAdd(&ssq[c], lq);
    }
    __syncthreads();
    if (tid < 32) {
        atomicAdd(&g_acc[tid], (double)ssum[tid]);
        atomicAdd(&g_acc[32 + tid], (double)ssq[tid]);
    }
}

// ---------------- finalize BN ----------------
__global__ void k_fin(int acc_off, int C, double inv_n,
                      const float* __restrict__ g, const float* __restrict__ be, int so) {
    int c = threadIdx.x;
    if (c < C) {
        double mean = g_acc[acc_off + c] * inv_n;
        double var = g_acc[acc_off + C + c] * inv_n - mean * mean;
        float s = g[c] * rsqrtf((float)var + 1e-5f);
        g_scale[so + c] = s;
        g_shift[so + c] = be[c] - (float)mean * s;
    }
}

// ---------------- bn0+relu(y0) -> conv1 (WMMA tf32), store y1, stats1 ----------
// block = half image, 256 threads (8 warps).
// GEMM: C[64co][98p] = W1[64][128k] x B[128k][98p]
//   B[k=(ci,ky,kx)][p=(oh,ow)] = bnrelu(y0)[ci][2oh+ky][2ow+kx]
// smem floats: B [128][136] 17408 | W [64][136] 8704 | ssum 64 | ssq 64
//   = 26240 fl = 104960 B (2 blocks/SM). C stored over B region after MMA.
__global__ void __launch_bounds__(256, 2) k_conv1(const float* __restrict__ w1,
                                                  const float* __restrict__ b1) {
    extern __shared__ float sm[];
    float* B    = sm;            // [128][136]
    float* W    = sm + 17408;    // [64][136]
    float* ssum = sm + 26112;    // 64
    float* ssq  = sm + 26176;    // 64

    int tid = threadIdx.x;
    int n = blockIdx.x >> 1;
    int half = blockIdx.x & 1;
    int r0 = half * 14;

    if (tid < 64) { ssum[tid] = 0.f; ssq[tid] = 0.f; }
    // weights -> smem (tf32-rounded), row-major [co][k], ldm 136
    for (int i = tid; i < 8192; i += 256) {
        int co = i >> 7, k = i & 127;
        W[co * 136 + k] = tf32r(w1[i]);
    }
    // zero B pad columns p=98..111
    for (int i = tid; i < 1792; i += 256) {
        B[(i / 14) * 136 + 98 + (i % 14)] = 0.f;
    }
    __syncthreads();

    // B-build: read y0 (14 rows), bn0+relu, parity permute, tf32
    for (int i = tid; i < 6272; i += 256) {      // 32ci x 14r x 14q
        int ci = i / 196, rem = i % 196;
        int r = rem / 14, q = rem % 14;
        float sc = g_scale[ci], sh = g_shift[ci];
        float2 v = *(const float2*)(g_y0 + ((size_t)(n * 32 + ci) * 28 + r0 + r) * 28 + 2 * q);
        float e = fmaxf(fmaf(v.x, sc, sh), 0.f);
        float o = fmaxf(fmaf(v.y, sc, sh), 0.f);
        int row = ci * 4 + (r & 1) * 2;          // + kx
        int p = (r >> 1) * 14 + q;
        B[row * 136 + p] = tf32r(e);
        B[(row + 1) * 136 + p] = tf32r(o);
    }
    __syncthreads();

    // WMMA: warps 0..6 each own one Ntile (16 p-cols), all 4 Mtiles
    int wpi = tid >> 5;
    wmma::fragment<wmma::accumulator, 16, 16, 8, float> cf[4];
    if (wpi < 7) {
#pragma unroll
        for (int m = 0; m < 4; m++) wmma::fill_fragment(cf[m], 0.f);
        wmma::fragment<wmma::matrix_a, 16, 16, 8, wmma::precision::tf32, wmma::row_major> af;
        wmma::fragment<wmma::matrix_b, 16, 16, 8, wmma::precision::tf32, wmma::row_major> bf;
#pragma unroll 4
        for (int ks = 0; ks < 16; ks++) {
            wmma::load_matrix_sync(bf, &B[ks * 8 * 136 + wpi * 16], 136);
#pragma unroll
            for (int m = 0; m < 4; m++) {
                wmma::load_matrix_sync(af, &W[m * 16 * 136 + ks * 8], 136);
                wmma::mma_sync(cf[m], af, bf, cf[m]);
            }
        }
    }
    __syncthreads();   // all B reads done -> store C over B region
    if (wpi < 7) {
#pragma unroll
        for (int m = 0; m < 4; m++)
            wmma::store_matrix_sync(&B[m * 16 * 136 + wpi * 16], cf[m], 136,
                                    wmma::mem_row_major);
    }
    __syncthreads();

    // bias + stats + y1 write
    {
        int co = tid >> 2, q = tid & 3;
        int p0 = q * 25, cnt = (q < 3) ? 25 : 23;
        float bias = b1[co];
        float ls = 0.f, lq = 0.f;
        float* dst = g_y1 + ((size_t)(n * 64 + co) * 14 + half * 7) * 14;
        const float* src = &B[co * 136 + p0];
#pragma unroll 5
        for (int i = 0; i < cnt; i++) {
            float v = src[i] + bias;
            dst[p0 + i] = v;
            ls += v; lq += v * v;
        }
        atomicAdd(&ssum[co], ls);
        atomicAdd(&ssq[co], lq);
    }
    __syncthreads();
    if (tid < 64) {
        atomicAdd(&g_acc[64 + tid], (double)ssum[tid]);
        atomicAdd(&g_acc[128 + tid], (double)ssq[tid]);
    }
}

// ---------------- fused bn1+relu -> conv2 (WMMA tf32), store y2, stats2 --------
// block = 1 image, 256 threads (8 warps), grid NB.
__global__ void __launch_bounds__(256, 2) k_conv2(const float* __restrict__ w2,
                                                  const float* __restrict__ b2) {
    extern __shared__ float sm[];
    float* B    = sm;            // [128][72]
    float* Wc   = sm + 9216;     // [128][136]
    float* ssum = sm + 26624;    // 128
    float* ssq  = sm + 26752;    // 128
    int tid = threadIdx.x;
    int n = blockIdx.x;
    if (tid < 128) { ssum[tid] = 0.f; ssq[tid] = 0.f; }

    // zero B pad columns p=49..63
    for (int i = tid; i < 1920; i += 256) {
        B[(i / 15) * 72 + 49 + (i % 15)] = 0.f;
    }

    int wpi = tid >> 5;
    int Nt = wpi & 3, Mg = wpi >> 2;
    wmma::fragment<wmma::accumulator, 16, 16, 8, float> cf[4];
#pragma unroll
    for (int m = 0; m < 4; m++) wmma::fill_fragment(cf[m], 0.f);
    wmma::fragment<wmma::matrix_a, 16, 16, 8, wmma::precision::tf32, wmma::row_major> af;
    wmma::fragment<wmma::matrix_b, 16, 16, 8, wmma::precision::tf32, wmma::row_major> bf;

    for (int kc = 0; kc < 2; kc++) {
        __syncthreads();
        for (int i = tid; i < 16384; i += 256) {
            int co = i >> 7, kl = i & 127;
            Wc[co * 136 + kl] = tf32r(w2[co * 256 + kc * 128 + kl]);
        }
        for (int i = tid; i < 3136; i += 256) {
            int ci = i / 98, rem = i % 98;
            int r = rem / 7, q = rem % 7;
            int cig = kc * 32 + ci;
            float sc = g_scale[32 + cig], sh = g_shift[32 + cig];
            float2 v = *(const float2*)(g_y1 + ((size_t)(n * 64 + cig)) * 196 + r * 14 + 2 * q);
            float e = fmaxf(fmaf(v.x, sc, sh), 0.f);
            float o = fmaxf(fmaf(v.y, sc, sh), 0.f);
            int rb = (ci * 4 + (r & 1) * 2) * 72 + (r >> 1) * 7 + q;
            B[rb] = tf32r(e);
            B[rb + 72] = tf32r(o);
        }
        __syncthreads();
#pragma unroll 4
        for (int ks = 0; ks < 16; ks++) {
            wmma::load_matrix_sync(bf, &B[ks * 8 * 72 + Nt * 16], 72);
#pragma unroll
            for (int m = 0; m < 4; m++) {
                int Mt = Mg * 4 + m;
                wmma::load_matrix_sync(af, &Wc[Mt * 16 * 136 + ks * 8], 136);
                wmma::mma_sync(cf[m], af, bf, cf[m]);
            }
        }
    }
    __syncthreads();
#pragma unroll
    for (int m = 0; m < 4; m++) {
        int Mt = Mg * 4 + m;
        wmma::store_matrix_sync(&B[Mt * 16 * 72 + Nt * 16], cf[m], 72,
                                wmma::mem_row_major);
    }
    __syncthreads();

    {
        int co = tid >> 1, hh = tid & 1;
        int p0 = hh * 25, cnt = hh ? 24 : 25;
        float bias = b2[co];
        float ls = 0.f, lq = 0.f;
        float* dst = g_y2 + (size_t)(n * 128 + co) * 49;
        const float* src = &B[co * 72 + p0];
#pragma unroll 5
        for (int i = 0; i < cnt; i++) {
            float v = src[i] + bias;
            dst[p0 + i] = v;
            ls += v; lq += v * v;
        }
        atomicAdd(&ssum[co], ls);
        atomicAdd(&ssq[co], lq);
    }
    __syncthreads();
    if (tid < 128) {
        atomicAdd(&g_acc[192 + tid], (double)ssum[tid]);
        atomicAdd(&g_acc[320 + tid], (double)ssq[tid]);
    }
}

// ---------------- bn2+relu + global avg pool + FC ----------------
__global__ void __launch_bounds__(128) k_head(const float* __restrict__ wfc,
                                              const float* __restrict__ bfc,
                                              float* __restrict__ out) {
    __shared__ float sraw[6272];
    __shared__ float pooled[128];
    int tid = threadIdx.x, n = blockIdx.x;
    const float* y2 = g_y2 + (size_t)n * 6272;
    for (int i = tid; i < 6272; i += 128) sraw[i] = y2[i];
    __syncthreads();
    {
        int c = tid;
        float sc = g_scale[96 + c], sh = g_shift[96 + c];
        float s = 0.f;
        const float* p = &sraw[c * 49];
#pragma unroll
        for (int i = 0; i < 49; i++) s += fmaxf(fmaf(p[i], sc, sh), 0.f);
        pooled[c] = s * (1.f / 49.f);
    }
    __syncthreads();
    if (tid < 10) {
        float o = bfc[tid];
        const float* wr = wfc + tid * 128;
#pragma unroll 8
        for (int c = 0; c < 128; c++) o = fmaf(pooled[c], wr[c], o);
        out[(size_t)n * 10 + tid] = o;
    }
}

// ---------------- launch ----------------
extern "C" void kernel_launch(void* const* d_in, const int* in_sizes, int n_in,
                              void* d_out, int out_size) {
    const float* x   = (const float*)d_in[0];
    const float* w0  = (const float*)d_in[1];
    const float* b0  = (const float*)d_in[2];
    const float* g0  = (const float*)d_in[3];
    const float* be0 = (const float*)d_in[4];
    const float* w1  = (const float*)d_in[5];
    const float* b1  = (const float*)d_in[6];
    const float* g1  = (const float*)d_in[7];
    const float* be1 = (const float*)d_in[8];
    const float* w2  = (const float*)d_in[9];
    const float* b2  = (const float*)d_in[10];
    const float* g2  = (const float*)d_in[11];
    const float* be2 = (const float*)d_in[12];
    const float* wfc = (const float*)d_in[13];
    const float* bfc = (const float*)d_in[14];
    float* out = (float*)d_out;

    cudaFuncSetAttribute(k_conv1, cudaFuncAttributeMaxDynamicSharedMemorySize, 104960);
    cudaFuncSetAttribute(k_conv2, cudaFuncAttributeMaxDynamicSharedMemorySize, 107520);

    k_zero<<<2, 256>>>();
    k_stats0<<<NB, 256>>>(x, w0, b0);
    k_fin<<<1, 128>>>(0, 32, 1.0 / (8192.0 * 784.0), g0, be0, 0);
    k_conv1<<<NB * 2, 256, 104960>>>(w1, b1);
    k_fin<<<1, 128>>>(64, 64, 1.0 / (8192.0 * 196.0), g1, be1, 32);
    k_conv2<<<NB, 256, 107520>>>(w2, b2);
    k_fin<<<1, 128>>>(192, 128, 1.0 / (8192.0 * 49.0), g2, be2, 96);
    k_head<<<NB, 128>>>(wfc, bfc, out);
}

// round 13
// speedup vs baseline: 1.1254x; 1.0587x over previous
#include <cuda_runtime.h>
#include <mma.h>
#include <math.h>

using namespace nvcuda;

#define NB 8192

// ---------------- device scratch ----------------
// g_y0: conv0 output in conv1-B layout [n][128][196] (822MB). Dead after k_conv1;
//       g_y2 aliases its head.
__device__ float  g_y0[(size_t)NB * 128 * 196];
// g_y1: conv1 output in conv2-B layout [n][256][49] (411MB)
__device__ float  g_y1[(size_t)NB * 256 * 49];
#define g_y2 g_y0                                     // conv2 pre-BN output [n][128][49]
__device__ double g_acc[448];
__device__ float  g_scale[224];
__device__ float  g_shift[224];

__device__ __forceinline__ float tf32r(float x) {
    float y;
    asm("cvt.rna.tf32.f32 %0, %1;" : "=f"(y) : "f"(x));
    return y;
}

// ---------------- zero stats ----------------
__global__ void k_zero() {
    int i = blockIdx.x * blockDim.x + threadIdx.x;
    if (i < 448) g_acc[i] = 0.0;
}

// ---------------- stage0: conv0 (+bias) -> y0 (permuted), stats ----------------
// y0 row = c*4 + (r&1)*2 + (col&1), p = (r>>1)*14 + (col>>1)
__global__ void __launch_bounds__(256) k_stats0(const float* __restrict__ x,
                                                const float* __restrict__ w0,
                                                const float* __restrict__ b0) {
    __shared__ float sx[30 * 28];
    __shared__ float sw[288];
    __shared__ float sb[32];
    __shared__ float ssum[32], ssq[32];
    int tid = threadIdx.x;
    int n = blockIdx.x;
    const float* xim = x + (size_t)n * 784;
    for (int i = tid; i < 840; i += 256) {
        int r = i / 28;
        sx[i] = (r >= 1 && r <= 28) ? xim[i - 28] : 0.f;
    }
    for (int i = tid; i < 288; i += 256) sw[i] = w0[i];
    if (tid < 32) { sb[tid] = b0[tid]; ssum[tid] = 0.f; ssq[tid] = 0.f; }
    __syncthreads();

#define LDROW(SR, X0, X1, X2) { const float* _p = &sx[(SR) * 28 + col]; \
        X0 = mL ? _p[-1] : 0.f; X1 = _p[0]; X2 = mR ? _p[1] : 0.f; }

    for (int task = tid; task < 896; task += 256) {
        int c = task / 28, col = task % 28;
        float w[9];
#pragma unroll
        for (int i = 0; i < 9; i++) w[i] = sw[c * 9 + i];
        float bias = sb[c];
        bool mL = col > 0, mR = col < 27;
        int rowbase = c * 4 + (col & 1);
        float* d0 = g_y0 + ((size_t)n * 128 + rowbase) * 196 + (col >> 1);
        float* d1 = d0 + 2 * 196;
        float a0, a1, a2, d00, d01, d02, e0, e1, e2;
        LDROW(0, a0, a1, a2);
        LDROW(1, d00, d01, d02);
        float ls = 0.f, lq = 0.f;
        for (int r = 0; r < 28; r++) {
            LDROW(r + 2, e0, e1, e2);
            float acc = bias;
            acc += w[0] * a0 + w[1] * a1 + w[2] * a2;
            acc += w[3] * d00 + w[4] * d01 + w[5] * d02;
            acc += w[6] * e0 + w[7] * e1 + w[8] * e2;
            ((r & 1) ? d1 : d0)[(r >> 1) * 14] = acc;
            ls += acc; lq += acc * acc;
            a0 = d00; a1 = d01; a2 = d02;
            d00 = e0; d01 = e1; d02 = e2;
        }
        atomicAdd(&ssum[c], ls);
        atomicAdd(&ssq[c], lq);
    }
    __syncthreads();
    if (tid < 32) {
        atomicAdd(&g_acc[tid], (double)ssum[tid]);
        atomicAdd(&g_acc[32 + tid], (double)ssq[tid]);
    }
}

// ---------------- finalize BN ----------------
__global__ void k_fin(int acc_off, int C, double inv_n,
                      const float* __restrict__ g, const float* __restrict__ be, int so) {
    int c = threadIdx.x;
    if (c < C) {
        double mean = g_acc[acc_off + c] * inv_n;
        double var = g_acc[acc_off + C + c] * inv_n - mean * mean;
        float s = g[c] * rsqrtf((float)var + 1e-5f);
        g_scale[so + c] = s;
        g_shift[so + c] = be[c] - (float)mean * s;
    }
}

// ---------------- bn0+relu(y0) -> conv1 (WMMA tf32) -> y1 (permuted), stats1 ----
// block = half image, 256 threads (8 warps).
// B[128][136] copied coalesced from y0 (p slice [half*98, half*98+98))
// smem floats: B 17408 | W [64][136] 8704 | ssum 64 | ssq 64 = 104960 B (2 blk/SM)
__global__ void __launch_bounds__(256, 2) k_conv1(const float* __restrict__ w1,
                                                  const float* __restrict__ b1) {
    extern __shared__ float sm[];
    float* B    = sm;            // [128][136]
    float* W    = sm + 17408;    // [64][136]
    float* ssum = sm + 26112;    // 64
    float* ssq  = sm + 26176;    // 64

    int tid = threadIdx.x;
    int n = blockIdx.x >> 1;
    int half = blockIdx.x & 1;

    if (tid < 64) { ssum[tid] = 0.f; ssq[tid] = 0.f; }
    for (int i = tid; i < 8192; i += 256) {
        int co = i >> 7, k = i & 127;
        W[co * 136 + k] = tf32r(w1[i]);
    }
    // zero B pad columns p=98..111
    for (int i = tid; i < 1792; i += 256) {
        B[(i / 14) * 136 + 98 + (i % 14)] = 0.f;
    }
    __syncthreads();

    // B-build: coalesced float2 copy + bn0 + relu + tf32
    const float* y0b = g_y0 + (size_t)n * 128 * 196 + half * 98;
    for (int idx = tid; idx < 6272; idx += 256) {   // 128 rows x 49 float2
        int row = idx / 49;
        int j = idx - row * 49;
        float sc = g_scale[row >> 2], sh = g_shift[row >> 2];
        float2 v = *(const float2*)(y0b + (size_t)row * 196 + 2 * j);
        B[row * 136 + 2 * j]     = tf32r(fmaxf(fmaf(v.x, sc, sh), 0.f));
        B[row * 136 + 2 * j + 1] = tf32r(fmaxf(fmaf(v.y, sc, sh), 0.f));
    }
    __syncthreads();

    // WMMA: warps 0..6 each own one Ntile (16 p-cols), all 4 Mtiles
    int wpi = tid >> 5;
    wmma::fragment<wmma::accumulator, 16, 16, 8, float> cf[4];
    if (wpi < 7) {
#pragma unroll
        for (int m = 0; m < 4; m++) wmma::fill_fragment(cf[m], 0.f);
        wmma::fragment<wmma::matrix_a, 16, 16, 8, wmma::precision::tf32, wmma::row_major> af;
        wmma::fragment<wmma::matrix_b, 16, 16, 8, wmma::precision::tf32, wmma::row_major> bf;
#pragma unroll 4
        for (int ks = 0; ks < 16; ks++) {
            wmma::load_matrix_sync(bf, &B[ks * 8 * 136 + wpi * 16], 136);
#pragma unroll
            for (int m = 0; m < 4; m++) {
                wmma::load_matrix_sync(af, &W[m * 16 * 136 + ks * 8], 136);
                wmma::mma_sync(cf[m], af, bf, cf[m]);
            }
        }
    }
    __syncthreads();   // all B reads done -> store C over B region
    if (wpi < 7) {
#pragma unroll
        for (int m = 0; m < 4; m++)
            wmma::store_matrix_sync(&B[m * 16 * 136 + wpi * 16], cf[m], 136,
                                    wmma::mem_row_major);
    }
    __syncthreads();

    // bias + stats + permuted y1 write ([n][256][49])
    {
        int co = tid >> 2, q = tid & 3;
        int p0 = q * 25, cnt = (q < 3) ? 25 : 23;
        float bias = b1[co];
        float ls = 0.f, lq = 0.f;
        const float* src = &B[co * 136 + p0];
        float* y1n = g_y1 + (size_t)n * 256 * 49;
#pragma unroll 5
        for (int i = 0; i < cnt; i++) {
            int p = p0 + i;
            int oh_l = p / 14, ow = p - oh_l * 14;
            int oh = half * 7 + oh_l;
            float v = src[i] + bias;
            int row = co * 4 + (oh & 1) * 2 + (ow & 1);
            int c2 = (oh >> 1) * 7 + (ow >> 1);
            y1n[row * 49 + c2] = v;
            ls += v; lq += v * v;
        }
        atomicAdd(&ssum[co], ls);
        atomicAdd(&ssq[co], lq);
    }
    __syncthreads();
    if (tid < 64) {
        atomicAdd(&g_acc[64 + tid], (double)ssum[tid]);
        atomicAdd(&g_acc[128 + tid], (double)ssq[tid]);
    }
}

// ---------------- bn1+relu(y1) -> conv2 (WMMA tf32), store y2, stats2 ----------
// block = 1 image, 256 threads (8 warps), grid NB.
__global__ void __launch_bounds__(256, 2) k_conv2(const float* __restrict__ w2,
                                                  const float* __restrict__ b2) {
    extern __shared__ float sm[];
    float* B    = sm;            // [128][72]
    float* Wc   = sm + 9216;     // [128][136]
    float* ssum = sm + 26624;    // 128
    float* ssq  = sm + 26752;    // 128
    int tid = threadIdx.x;
    int n = blockIdx.x;
    if (tid < 128) { ssum[tid] = 0.f; ssq[tid] = 0.f; }

    // zero B pad columns p=49..63
    for (int i = tid; i < 1920; i += 256) {
        B[(i / 15) * 72 + 49 + (i % 15)] = 0.f;
    }

    int wpi = tid >> 5;
    int Nt = wpi & 3, Mg = wpi >> 2;
    wmma::fragment<wmma::accumulator, 16, 16, 8, float> cf[4];
#pragma unroll
    for (int m = 0; m < 4; m++) wmma::fill_fragment(cf[m], 0.f);
    wmma::fragment<wmma::matrix_a, 16, 16, 8, wmma::precision::tf32, wmma::row_major> af;
    wmma::fragment<wmma::matrix_b, 16, 16, 8, wmma::precision::tf32, wmma::row_major> bf;

    const float* y1n = g_y1 + (size_t)n * 256 * 49;
    for (int kc = 0; kc < 2; kc++) {
        __syncthreads();
        for (int i = tid; i < 16384; i += 256) {
            int co = i >> 7, kl = i & 127;
            Wc[co * 136 + kl] = tf32r(w2[co * 256 + kc * 128 + kl]);
        }
        // B-build: coalesced copy + bn1 + relu + tf32
        for (int idx = tid; idx < 6272; idx += 256) {   // 128 rows x 49 cols
            int rb = idx / 49;
            int j = idx - rb * 49;
            int gr = kc * 128 + rb;
            float sc = g_scale[32 + (gr >> 2)], sh = g_shift[32 + (gr >> 2)];
            float v = y1n[gr * 49 + j];
            B[rb * 72 + j] = tf32r(fmaxf(fmaf(v, sc, sh), 0.f));
        }
        __syncthreads();
#pragma unroll 4
        for (int ks = 0; ks < 16; ks++) {
            wmma::load_matrix_sync(bf, &B[ks * 8 * 72 + Nt * 16], 72);
#pragma unroll
            for (int m = 0; m < 4; m++) {
                int Mt = Mg * 4 + m;
                wmma::load_matrix_sync(af, &Wc[Mt * 16 * 136 + ks * 8], 136);
                wmma::mma_sync(cf[m], af, bf, cf[m]);
            }
        }
    }
    __syncthreads();
#pragma unroll
    for (int m = 0; m < 4; m++) {
        int Mt = Mg * 4 + m;
        wmma::store_matrix_sync(&B[Mt * 16 * 72 + Nt * 16], cf[m], 72,
                                wmma::mem_row_major);
    }
    __syncthreads();

    {
        int co = tid >> 1, hh = tid & 1;
        int p0 = hh * 25, cnt = hh ? 24 : 25;
        float bias = b2[co];
        float ls = 0.f, lq = 0.f;
        float* dst = g_y2 + (size_t)(n * 128 + co) * 49;
        const float* src = &B[co * 72 + p0];
#pragma unroll 5
        for (int i = 0; i < cnt; i++) {
            float v = src[i] + bias;
            dst[p0 + i] = v;
            ls += v; lq += v * v;
        }
        atomicAdd(&ssum[co], ls);
        atomicAdd(&ssq[co], lq);
    }
    __syncthreads();
    if (tid < 128) {
        atomicAdd(&g_acc[192 + tid], (double)ssum[tid]);
        atomicAdd(&g_acc[320 + tid], (double)ssq[tid]);
    }
}

// ---------------- bn2+relu + global avg pool + FC ----------------
__global__ void __launch_bounds__(128) k_head(const float* __restrict__ wfc,
                                              const float* __restrict__ bfc,
                                              float* __restrict__ out) {
    __shared__ float sraw[6272];
    __shared__ float pooled[128];
    int tid = threadIdx.x, n = blockIdx.x;
    const float* y2 = g_y2 + (size_t)n * 6272;
    for (int i = tid; i < 6272; i += 128) sraw[i] = y2[i];
    __syncthreads();
    {
        int c = tid;
        float sc = g_scale[96 + c], sh = g_shift[96 + c];
        float s = 0.f;
        const float* p = &sraw[c * 49];
#pragma unroll
        for (int i = 0; i < 49; i++) s += fmaxf(fmaf(p[i], sc, sh), 0.f);
        pooled[c] = s * (1.f / 49.f);
    }
    __syncthreads();
    if (tid < 10) {
        float o = bfc[tid];
        const float* wr = wfc + tid * 128;
#pragma unroll 8
        for (int c = 0; c < 128; c++) o = fmaf(pooled[c], wr[c], o);
        out[(size_t)n * 10 + tid] = o;
    }
}

// ---------------- launch ----------------
extern "C" void kernel_launch(void* const* d_in, const int* in_sizes, int n_in,
                              void* d_out, int out_size) {
    const float* x   = (const float*)d_in[0];
    const float* w0  = (const float*)d_in[1];
    const float* b0  = (const float*)d_in[2];
    const float* g0  = (const float*)d_in[3];
    const float* be0 = (const float*)d_in[4];
    const float* w1  = (const float*)d_in[5];
    const float* b1  = (const float*)d_in[6];
    const float* g1  = (const float*)d_in[7];
    const float* be1 = (const float*)d_in[8];
    const float* w2  = (const float*)d_in[9];
    const float* b2  = (const float*)d_in[10];
    const float* g2  = (const float*)d_in[11];
    const float* be2 = (const float*)d_in[12];
    const float* wfc = (const float*)d_in[13];
    const float* bfc = (const float*)d_in[14];
    float* out = (float*)d_out;

    cudaFuncSetAttribute(k_conv1, cudaFuncAttributeMaxDynamicSharedMemorySize, 104960);
    cudaFuncSetAttribute(k_conv2, cudaFuncAttributeMaxDynamicSharedMemorySize, 107520);

    k_zero<<<2, 256>>>();
    k_stats0<<<NB, 256>>>(x, w0, b0);
    k_fin<<<1, 128>>>(0, 32, 1.0 / (8192.0 * 784.0), g0, be0, 0);
    k_conv1<<<NB * 2, 256, 104960>>>(w1, b1);
    k_fin<<<1, 128>>>(64, 64, 1.0 / (8192.0 * 196.0), g1, be1, 32);
    k_conv2<<<NB, 256, 107520>>>(w2, b2);
    k_fin<<<1, 128>>>(192, 128, 1.0 / (8192.0 * 49.0), g2, be2, 96);
    k_head<<<NB, 128>>>(wfc, bfc, out);
}